// round 2
// baseline (speedup 1.0000x reference)
#include <cuda_runtime.h>
#include <math.h>

// ---------------- problem constants ----------------
#define NN   200000
#define NI   64
#define NFD  128
#define NE   256
#define BB   16
#define KK   27
#define KDD  8
#define NDD  (NN / 8)        // 25000

#define TILE_M 128
#define CHUNK  16
#define THREADS 512
#define STATS_BLOCKS 512

// ---------------- scratch (device globals; no allocation allowed) ----------------
__device__ float g_a [(size_t)NN * NFD];   // activations
__device__ float g_h [(size_t)NN * NFD];   // h after conv1 + film
__device__ float g_h2[(size_t)NN * NFD];   // h after conv2 + idconv
__device__ float g_part[STATS_BLOCKS * 2 * NFD];
__device__ float g_mv[2 * NFD];            // per-channel fused scale / shift
__device__ float g_tp[BB * 2 * NFD];       // time projection [16, 256]

__device__ __forceinline__ float silu_f(float x) {
    return x / (1.0f + expf(-x));
}

// ---------------- BN statistics: pass 1 (deterministic partial sums) ----------------
template<int C>
__global__ void bn_stats_kernel(const float* __restrict__ X, int n, float* __restrict__ part) {
    constexpr int G = 256 / C;
    __shared__ float sh[512];
    int t = threadIdx.x;
    int c = t % C, g = t / C;
    float s = 0.f, s2 = 0.f;
    for (int r = blockIdx.x * G + g; r < n; r += gridDim.x * G) {
        float v = X[(size_t)r * C + c];
        s += v; s2 += v * v;
    }
    sh[t] = s; sh[256 + t] = s2;
    __syncthreads();
    if (t < C) {
        float a = 0.f, b = 0.f;
        #pragma unroll
        for (int gg = 0; gg < G; ++gg) { a += sh[gg * C + t]; b += sh[256 + gg * C + t]; }
        part[blockIdx.x * (2 * C) + t]     = a;
        part[blockIdx.x * (2 * C) + C + t] = b;
    }
}

// ---------------- BN statistics: pass 2 (fold gamma/beta into scale+shift) ----------------
template<int C>
__global__ void bn_finalize_kernel(const float* __restrict__ part, int nblocks, float invn,
                                   const float* __restrict__ g, const float* __restrict__ be,
                                   float* __restrict__ mv) {
    int c = threadIdx.x;
    if (c >= C) return;
    float s = 0.f, s2 = 0.f;
    for (int b = 0; b < nblocks; ++b) {
        s  += part[b * 2 * C + c];
        s2 += part[b * 2 * C + C + c];
    }
    float mean = s * invn;
    float var  = s2 * invn - mean * mean;
    float istd = rsqrtf(var + 1e-5f);
    float A = istd * g[c];
    mv[c]     = A;
    mv[C + c] = be[c] - mean * A;
}

// ---------------- apply BN (fused) + SiLU, vectorized ----------------
template<int C>
__global__ void bn_apply_silu_kernel(const float4* __restrict__ X, const float* __restrict__ mv,
                                     float4* __restrict__ Y, int n4) {
    int i = blockIdx.x * 256 + threadIdx.x;
    if (i >= n4) return;
    int f = (i & (C / 4 - 1)) * 4;
    float4 v = X[i];
    float4 o;
    o.x = silu_f(fmaf(v.x, mv[f + 0], mv[C + f + 0]));
    o.y = silu_f(fmaf(v.y, mv[f + 1], mv[C + f + 1]));
    o.z = silu_f(fmaf(v.z, mv[f + 2], mv[C + f + 2]));
    o.w = silu_f(fmaf(v.w, mv[f + 3], mv[C + f + 3]));
    Y[i] = o;
}

// ---------------- time projection: tp = silu(t) @ Wt + bt   ([16,256]x[256,256]) ----------------
__global__ void tproj_kernel(const float* __restrict__ T, const float* __restrict__ Wt,
                             const float* __restrict__ bt, float* __restrict__ tp) {
    __shared__ float ts[BB * NE];
    int t = threadIdx.x;
    for (int l = t; l < BB * NE; l += 256) ts[l] = silu_f(T[l]);
    __syncthreads();
    float acc[BB];
    #pragma unroll
    for (int b = 0; b < BB; ++b) acc[b] = 0.f;
    for (int e = 0; e < NE; ++e) {
        float w = Wt[e * 256 + t];
        #pragma unroll
        for (int b = 0; b < BB; ++b) acc[b] = fmaf(ts[b * NE + e], w, acc[b]);
    }
    float bias = bt[t];
    #pragma unroll
    for (int b = 0; b < BB; ++b) tp[b * 256 + t] = acc[b] + bias;
}

// ---------------- FiLM: h = (1+scale[b_idx])*h + shift[b_idx] ----------------
__global__ void film_kernel(float4* __restrict__ H, const int* __restrict__ b_idx,
                            const float* __restrict__ tp, int total4) {
    int i = blockIdx.x * 256 + threadIdx.x;
    if (i >= total4) return;
    int n = i >> 5;             // 32 float4 per row (NF=128)
    int f = (i & 31) * 4;
    int b = b_idx[n];
    const float* sp  = tp + b * 256 + f;
    const float* shp = sp + NFD;
    float4 h = H[i];
    h.x = fmaf(sp[0], h.x, h.x) + shp[0];
    h.y = fmaf(sp[1], h.y, h.y) + shp[1];
    h.z = fmaf(sp[2], h.z, h.z) + shp[2];
    h.w = fmaf(sp[3], h.w, h.w) + shp[3];
    H[i] = h;
}

// ---------------- gather-GEMM v2 (sparse conv) ----------------
// 128x128 block tile, 512 threads, 4 rows x 8 cols per thread, f32x2 FMAs,
// duplicated X in smem (direct LDS.64), register-prefetch software pipeline.
#define XROW 34   // padded row stride (floats) for duplicated Xs

template<int CIN, bool ACCUM, bool HAS_BIAS, bool HAS_NBR>
__global__ __launch_bounds__(THREADS)
void conv_kernel(const float* __restrict__ X, const float* __restrict__ W,
                 const float* __restrict__ bias, const int* __restrict__ nbr,
                 float* __restrict__ out, int M, int K) {
    __shared__ float Xs[TILE_M * XROW];                 // duplicated pairs, padded
    __shared__ float Ws[CHUNK * NFD];

    const int t  = threadIdx.x;
    const int tx = t & 15;             // col group: cols 4*tx + 64*j
    const int ty = t >> 4;             // row group: rows ty*4 + r  (ty 0..31)
    const int rowBase = blockIdx.x * TILE_M;

    constexpr int CPK = CIN / CHUNK;
    const int total = K * CPK;

    // gather roles
    const int gc = t & 15;             // column within chunk
    const int gty = t >> 4;            // row base (+32*i)
    // weight roles
    const int wc = t >> 5;             // chunk row 0..15
    const int wf = (t & 31) * 4;       // 4-col group

    unsigned long long acc[4][4];      // [r][j*2+p]
    #pragma unroll
    for (int r = 0; r < 4; ++r)
        #pragma unroll
        for (int q = 0; q < 4; ++q) acc[r][q] = 0ULL;

    // ---- prefetch chunk 0 ----
    int   idxv[4];
    float xv[4];
    float4 wv;
    {
        const int k = 0, cc = 0;
        wv = *(const float4*)(W + ((size_t)(k * CIN + cc + wc)) * NFD + wf);
        #pragma unroll
        for (int i = 0; i < 4; ++i) {
            int gr = rowBase + gty + 32 * i;
            int idx;
            if (HAS_NBR) idx = (gr < M) ? nbr[(size_t)k * M + gr] : -1;
            else         idx = (gr < M) ? gr : -1;
            idxv[i] = idx;
        }
        #pragma unroll
        for (int i = 0; i < 4; ++i)
            xv[i] = (idxv[i] >= 0) ? X[(size_t)idxv[i] * CIN + cc + gc] : 0.f;
    }

    float* xbase = Xs + (ty * 4) * XROW;   // this thread's first compute row

    for (int kc = 0; kc < total; ++kc) {
        __syncthreads();
        // store prefetched chunk to smem
        *(float4*)(Ws + wc * NFD + wf) = wv;
        #pragma unroll
        for (int i = 0; i < 4; ++i) {
            float v = xv[i];
            *(float2*)(Xs + (gty + 32 * i) * XROW + 2 * gc) = make_float2(v, v);
        }
        __syncthreads();

        const bool have_next = (kc + 1) < total;
        int nk = 0, ncc = 0;
        if (have_next) {
            int kn = kc + 1;
            nk  = kn / CPK;
            ncc = (kn - nk * CPK) * CHUNK;
            wv = *(const float4*)(W + ((size_t)(nk * CIN + ncc + wc)) * NFD + wf);
            #pragma unroll
            for (int i = 0; i < 4; ++i) {
                int gr = rowBase + gty + 32 * i;
                int idx;
                if (HAS_NBR) idx = (gr < M) ? nbr[(size_t)nk * M + gr] : -1;
                else         idx = (gr < M) ? gr : -1;
                idxv[i] = idx;
            }
        }

        // compute first half while idx loads are in flight
        #pragma unroll
        for (int c = 0; c < CHUNK / 2; ++c) {
            unsigned long long xx[4];
            #pragma unroll
            for (int r = 0; r < 4; ++r)
                xx[r] = *(const unsigned long long*)(xbase + r * XROW + 2 * c);
            ulonglong2 w0 = *(const ulonglong2*)(Ws + c * NFD + 4 * tx);
            ulonglong2 w1 = *(const ulonglong2*)(Ws + c * NFD + 4 * tx + 64);
            #pragma unroll
            for (int r = 0; r < 4; ++r) {
                asm("fma.rn.f32x2 %0, %1, %2, %0;" : "+l"(acc[r][0]) : "l"(xx[r]), "l"(w0.x));
                asm("fma.rn.f32x2 %0, %1, %2, %0;" : "+l"(acc[r][1]) : "l"(xx[r]), "l"(w0.y));
                asm("fma.rn.f32x2 %0, %1, %2, %0;" : "+l"(acc[r][2]) : "l"(xx[r]), "l"(w1.x));
                asm("fma.rn.f32x2 %0, %1, %2, %0;" : "+l"(acc[r][3]) : "l"(xx[r]), "l"(w1.y));
            }
        }

        // dependent gather loads for next chunk
        if (have_next) {
            #pragma unroll
            for (int i = 0; i < 4; ++i)
                xv[i] = (idxv[i] >= 0) ? X[(size_t)idxv[i] * CIN + ncc + gc] : 0.f;
        }

        // compute second half
        #pragma unroll
        for (int c = CHUNK / 2; c < CHUNK; ++c) {
            unsigned long long xx[4];
            #pragma unroll
            for (int r = 0; r < 4; ++r)
                xx[r] = *(const unsigned long long*)(xbase + r * XROW + 2 * c);
            ulonglong2 w0 = *(const ulonglong2*)(Ws + c * NFD + 4 * tx);
            ulonglong2 w1 = *(const ulonglong2*)(Ws + c * NFD + 4 * tx + 64);
            #pragma unroll
            for (int r = 0; r < 4; ++r) {
                asm("fma.rn.f32x2 %0, %1, %2, %0;" : "+l"(acc[r][0]) : "l"(xx[r]), "l"(w0.x));
                asm("fma.rn.f32x2 %0, %1, %2, %0;" : "+l"(acc[r][1]) : "l"(xx[r]), "l"(w0.y));
                asm("fma.rn.f32x2 %0, %1, %2, %0;" : "+l"(acc[r][2]) : "l"(xx[r]), "l"(w1.x));
                asm("fma.rn.f32x2 %0, %1, %2, %0;" : "+l"(acc[r][3]) : "l"(xx[r]), "l"(w1.y));
            }
        }
    }

    // ---- epilogue ----
    float b0[8];
    if (HAS_BIAS) {
        #pragma unroll
        for (int q = 0; q < 4; ++q) { b0[q] = bias[4 * tx + q]; b0[4 + q] = bias[4 * tx + 64 + q]; }
    }
    #pragma unroll
    for (int r = 0; r < 4; ++r) {
        int gr = rowBase + ty * 4 + r;
        if (gr >= M) continue;
        #pragma unroll
        for (int j = 0; j < 2; ++j) {
            float4 o;
            float lo, hi;
            asm("mov.b64 {%0, %1}, %2;" : "=f"(lo), "=f"(hi) : "l"(acc[r][2 * j + 0]));
            o.x = lo; o.y = hi;
            asm("mov.b64 {%0, %1}, %2;" : "=f"(lo), "=f"(hi) : "l"(acc[r][2 * j + 1]));
            o.z = lo; o.w = hi;
            if (HAS_BIAS) { o.x += b0[4 * j]; o.y += b0[4 * j + 1]; o.z += b0[4 * j + 2]; o.w += b0[4 * j + 3]; }
            float4* op = (float4*)(out + (size_t)gr * NFD + 4 * tx + 64 * j);
            if (ACCUM) {
                float4 p = *op;
                o.x += p.x; o.y += p.y; o.z += p.z; o.w += p.w;
            }
            *op = o;
        }
    }
}

// ---------------- launch ----------------
extern "C" void kernel_launch(void* const* d_in, const int* in_sizes, int n_in,
                              void* d_out, int out_size) {
    const float* x     = (const float*)d_in[0];
    const float* t     = (const float*)d_in[1];
    const int*   b_idx = (const int*)  d_in[2];
    const int*   nbr   = (const int*)  d_in[3];
    const int*   nbrd  = (const int*)  d_in[4];
    const float* g1    = (const float*)d_in[5];
    const float* be1   = (const float*)d_in[6];
    const float* W1    = (const float*)d_in[7];
    const float* b1    = (const float*)d_in[8];
    const float* Wt    = (const float*)d_in[9];
    const float* bt    = (const float*)d_in[10];
    const float* g2    = (const float*)d_in[11];
    const float* be2   = (const float*)d_in[12];
    const float* W2    = (const float*)d_in[13];
    const float* b2    = (const float*)d_in[14];
    const float* Wid   = (const float*)d_in[15];
    const float* bid   = (const float*)d_in[16];
    const float* Wd    = (const float*)d_in[17];
    float* out = (float*)d_out;

    float *pa, *ph, *ph2, *ppart, *pmv, *ptp;
    cudaGetSymbolAddress((void**)&pa,    g_a);
    cudaGetSymbolAddress((void**)&ph,    g_h);
    cudaGetSymbolAddress((void**)&ph2,   g_h2);
    cudaGetSymbolAddress((void**)&ppart, g_part);
    cudaGetSymbolAddress((void**)&pmv,   g_mv);
    cudaGetSymbolAddress((void**)&ptp,   g_tp);

    const float invn = 1.0f / (float)NN;
    const int convGrid = (NN + TILE_M - 1) / TILE_M;   // 1563
    const int downGrid = (NDD + TILE_M - 1) / TILE_M;  // 196

    // ---- BN1(x) + SiLU -> a1 ----
    bn_stats_kernel<NI><<<STATS_BLOCKS, 256>>>(x, NN, ppart);
    bn_finalize_kernel<NI><<<1, NI>>>(ppart, STATS_BLOCKS, invn, g1, be1, pmv);
    {
        int n4 = NN * NI / 4;
        bn_apply_silu_kernel<NI><<<(n4 + 255) / 256, 256>>>((const float4*)x, pmv,
                                                            (float4*)pa, n4);
    }
    // ---- conv1 -> h ----
    conv_kernel<NI, false, true, true><<<convGrid, THREADS>>>(pa, W1, b1, nbr, ph, NN, KK);
    // ---- time projection + FiLM ----
    tproj_kernel<<<1, 256>>>(t, Wt, bt, ptp);
    {
        int n4 = NN * NFD / 4;
        film_kernel<<<(n4 + 255) / 256, 256>>>((float4*)ph, b_idx, ptp, n4);
    }
    // ---- BN2(h) + SiLU -> a2 ----
    bn_stats_kernel<NFD><<<STATS_BLOCKS, 256>>>(ph, NN, ppart);
    bn_finalize_kernel<NFD><<<1, NFD>>>(ppart, STATS_BLOCKS, invn, g2, be2, pmv);
    {
        int n4 = NN * NFD / 4;
        bn_apply_silu_kernel<NFD><<<(n4 + 255) / 256, 256>>>((const float4*)ph, pmv,
                                                             (float4*)pa, n4);
    }
    // ---- conv2 -> h2 ----
    conv_kernel<NFD, false, true, true><<<convGrid, THREADS>>>(pa, W2, b2, nbr, ph2, NN, KK);
    // ---- idconv residual: h2 += x @ Wid + bid ----
    conv_kernel<NI, true, true, false><<<convGrid, THREADS>>>(x, Wid, bid, nullptr, ph2, NN, 1);
    // ---- strided down conv -> out [ND, NF] ----
    conv_kernel<NFD, false, false, true><<<downGrid, THREADS>>>(ph2, Wd, nullptr, nbrd, out,
                                                                NDD, KDD);
    (void)in_sizes; (void)n_in; (void)out_size;
}

// round 4
// speedup vs baseline: 3.7641x; 3.7641x over previous
#include <cuda_runtime.h>
#include <math.h>
#include <stdint.h>

// ---------------- problem constants ----------------
#define NN   200000
#define NI   64
#define NFD  128
#define NE   256
#define BB   16
#define KK   27
#define KDD  8
#define NDD  (NN / 8)        // 25000

#define STATS_BLOCKS 512
#define TILE_M 128
#define AW 36                 // padded smem row stride (floats)
#define CONV_SMEM (2 * (128 * AW) * 4 * 2)   // A(2 bufs) + B(2 bufs) = 73728 B

// ---------------- scratch (device globals; no allocation allowed) ----------------
__device__ float g_a  [(size_t)NN * NFD];
__device__ float g_h  [(size_t)NN * NFD];
__device__ float g_h2 [(size_t)NN * NFD];
__device__ float g_part[STATS_BLOCKS * 2 * NFD];
__device__ float g_mv [2 * NFD];
__device__ float g_tp [BB * 2 * NFD];
__device__ float g_W1T[27 * 128 * 64];
__device__ float g_W2T[27 * 128 * 128];
__device__ float g_WiT[128 * 64];
__device__ float g_WdT[8 * 128 * 128];

// ---------------- helpers ----------------
__device__ __forceinline__ float silu_f(float x) { return x / (1.0f + expf(-x)); }

__device__ __forceinline__ float tf32r(float v) {
    unsigned u;
    asm("cvt.rna.tf32.f32 %0, %1;" : "=r"(u) : "f"(v));
    return __uint_as_float(u);
}

__device__ __forceinline__ uint32_t smem_u32(const void* p) {
    uint32_t a;
    asm("{ .reg .u64 t; cvta.to.shared.u64 t, %1; cvt.u32.u64 %0, t; }" : "=r"(a) : "l"(p));
    return a;
}

__device__ __forceinline__ void ldsm4(uint32_t* d, uint32_t addr) {
    asm volatile("ldmatrix.sync.aligned.m8n8.x4.shared.b16 {%0,%1,%2,%3}, [%4];"
                 : "=r"(d[0]), "=r"(d[1]), "=r"(d[2]), "=r"(d[3]) : "r"(addr));
}

__device__ __forceinline__ void mma_tf32(float* c, const uint32_t* a, const uint32_t* b) {
    asm volatile("mma.sync.aligned.m16n8k8.row.col.f32.tf32.tf32.f32 "
                 "{%0,%1,%2,%3}, {%4,%5,%6,%7}, {%8,%9}, {%0,%1,%2,%3};"
                 : "+f"(c[0]), "+f"(c[1]), "+f"(c[2]), "+f"(c[3])
                 : "r"(a[0]), "r"(a[1]), "r"(a[2]), "r"(a[3]), "r"(b[0]), "r"(b[1]));
}

// smem word offset for element (row r, float col c in 0..31):
//   r*AW + ((c>>4) ^ (r&1))*16 + (c&15)   -- conflict-free for ldmatrix AND 16B stores
__device__ __forceinline__ int sm_off(int r, int half) {
    return r * AW + ((half ^ (r & 1)) << 4);
}

// ---------------- BN statistics ----------------
template<int C>
__global__ void bn_stats_kernel(const float* __restrict__ X, int n, float* __restrict__ part) {
    constexpr int G = 256 / C;
    __shared__ float sh[512];
    int t = threadIdx.x;
    int c = t % C, g = t / C;
    float s = 0.f, s2 = 0.f;
    for (int r = blockIdx.x * G + g; r < n; r += gridDim.x * G) {
        float v = X[(size_t)r * C + c];
        s += v; s2 += v * v;
    }
    sh[t] = s; sh[256 + t] = s2;
    __syncthreads();
    if (t < C) {
        float a = 0.f, b = 0.f;
        #pragma unroll
        for (int gg = 0; gg < G; ++gg) { a += sh[gg * C + t]; b += sh[256 + gg * C + t]; }
        part[blockIdx.x * (2 * C) + t]     = a;
        part[blockIdx.x * (2 * C) + C + t] = b;
    }
}

template<int C>
__global__ void bn_finalize_kernel(const float* __restrict__ part, int nblocks, float invn,
                                   const float* __restrict__ g, const float* __restrict__ be,
                                   float* __restrict__ mv) {
    int c = threadIdx.x;
    if (c >= C) return;
    float s = 0.f, s2 = 0.f;
    for (int b = 0; b < nblocks; ++b) {
        s  += part[b * 2 * C + c];
        s2 += part[b * 2 * C + C + c];
    }
    float mean = s * invn;
    float var  = s2 * invn - mean * mean;
    float istd = rsqrtf(var + 1e-5f);
    float A = istd * g[c];
    mv[c]     = A;
    mv[C + c] = be[c] - mean * A;
}

template<int C>
__global__ void bn_apply_silu_kernel(const float4* __restrict__ X, const float* __restrict__ mv,
                                     float4* __restrict__ Y, int n4) {
    int i = blockIdx.x * 256 + threadIdx.x;
    if (i >= n4) return;
    int f = (i & (C / 4 - 1)) * 4;
    float4 v = X[i];
    float4 o;
    o.x = silu_f(fmaf(v.x, mv[f + 0], mv[C + f + 0]));
    o.y = silu_f(fmaf(v.y, mv[f + 1], mv[C + f + 1]));
    o.z = silu_f(fmaf(v.z, mv[f + 2], mv[C + f + 2]));
    o.w = silu_f(fmaf(v.w, mv[f + 3], mv[C + f + 3]));
    Y[i] = o;
}

// ---------------- time projection ----------------
__global__ void tproj_kernel(const float* __restrict__ T, const float* __restrict__ Wt,
                             const float* __restrict__ bt, float* __restrict__ tp) {
    __shared__ float ts[BB * NE];
    int t = threadIdx.x;
    for (int l = t; l < BB * NE; l += 256) ts[l] = silu_f(T[l]);
    __syncthreads();
    float acc[BB];
    #pragma unroll
    for (int b = 0; b < BB; ++b) acc[b] = 0.f;
    for (int e = 0; e < NE; ++e) {
        float w = Wt[e * 256 + t];
        #pragma unroll
        for (int b = 0; b < BB; ++b) acc[b] = fmaf(ts[b * NE + e], w, acc[b]);
    }
    float bias = bt[t];
    #pragma unroll
    for (int b = 0; b < BB; ++b) tp[b * 256 + t] = acc[b] + bias;
}

// ---------------- weight prep: transpose [K][CI][128] -> rna-tf32 [K][128][CI] ----------------
template<int CI>
__global__ void wprep_kernel(const float* __restrict__ W, float* __restrict__ WT) {
    __shared__ float tile[32][33];
    int k   = blockIdx.z;
    int ci0 = blockIdx.y * 32;
    int co0 = blockIdx.x * 32;
    int tx = threadIdx.x, ty = threadIdx.y;   // 32 x 8
    #pragma unroll
    for (int j = 0; j < 4; ++j) {
        int ci = ci0 + ty + j * 8;
        tile[ty + j * 8][tx] = W[((size_t)k * CI + ci) * 128 + co0 + tx];
    }
    __syncthreads();
    #pragma unroll
    for (int j = 0; j < 4; ++j) {
        int co = co0 + ty + j * 8;
        WT[((size_t)k * 128 + co) * CI + ci0 + tx] = tf32r(tile[tx][ty + j * 8]);
    }
}

// ---------------- mma.sync tf32 gather-GEMM (sparse conv) ----------------
// MODE: 0 = plain, 1 = bias + FiLM fused, 2 = bias+bias2 with 2 extra idconv chunks
struct Chunk {
    const float* a;   // activation source
    int aCIN;         // its row stride
    const int* nb;    // neighbor row (nullptr = identity)
    const float* b;   // weight chunk base (row stride brs), already offset by cc
    int brs;
    int cc;           // channel offset into activation row
};

template<int CIN, int MODE>
__global__ __launch_bounds__(256, 2)
void conv_mma_kernel(const float* __restrict__ X, const int* __restrict__ nbr,
                     const float* __restrict__ BT, const float* __restrict__ bias,
                     const float* __restrict__ bias2, const float* __restrict__ tp,
                     const int* __restrict__ b_idx, const float* __restrict__ Xid,
                     const float* __restrict__ WiT,
                     float* __restrict__ out, int M, int K) {
    extern __shared__ float sm[];
    const uint32_t smA = smem_u32(sm);            // A: 2 x 18432 B
    const uint32_t smB = smA + 36864;             // B: 2 x 18432 B

    constexpr int CPK = CIN / 32;
    const int MAIN  = K * CPK;
    const int TOTAL = MAIN + ((MODE == 2) ? 2 : 0);

    const int t = threadIdx.x;
    const int lane = t & 31, w = t >> 5;
    const int warpM = w >> 2, warpN = w & 3;
    const int rowBase = blockIdx.x * TILE_M;

    // loader roles
    const int lr_ = t >> 1;          // row 0..127
    const int lh  = t & 1;           // half (16 floats)

    // ldmatrix address components
    const int g  = lane >> 3, lg = lane & 7;
    const int arow = warpM * 64 + lg + (g & 1) * 8;       // + mt*16
    const int acg  = (g >> 1) * 4;                        // A col within k8
    const int ap   = arow & 1;
    const int brow = warpN * 32 + lg + (g >> 1) * 8;      // + p*16
    const int bcg  = (g & 1) * 4;
    const int bp   = brow & 1;

    float acc[4][4][4];
    #pragma unroll
    for (int i = 0; i < 4; ++i)
        #pragma unroll
        for (int j = 0; j < 4; ++j)
            #pragma unroll
            for (int q = 0; q < 4; ++q) acc[i][j][q] = 0.f;

    auto decode = [&](int c) -> Chunk {
        Chunk ch;
        if (MODE != 2 || c < MAIN) {
            int k  = c / CPK;
            int cc = (c - k * CPK) * 32;
            ch.a = X; ch.aCIN = CIN; ch.cc = cc;
            ch.nb = nbr + (size_t)k * M;
            ch.b = BT + ((size_t)k * 128) * CIN + cc; ch.brs = CIN;
        } else {
            int cc = (c - MAIN) * 32;
            ch.a = Xid; ch.aCIN = 64; ch.cc = cc;
            ch.nb = nullptr;
            ch.b = WiT + cc; ch.brs = 64;
        }
        return ch;
    };

    float4 va[4];
    auto ldA = [&](const Chunk& ch) {
        int row = rowBase + lr_;
        int idx = -1;
        if (row < M) idx = ch.nb ? ch.nb[row] : row;
        if (idx >= 0) {
            const float4* p = (const float4*)(ch.a + (size_t)idx * ch.aCIN + ch.cc + lh * 16);
            va[0] = p[0]; va[1] = p[1]; va[2] = p[2]; va[3] = p[3];
        } else {
            va[0] = va[1] = va[2] = va[3] = make_float4(0.f, 0.f, 0.f, 0.f);
        }
    };
    auto stsA = [&](int bu) {
        float* dst = sm + bu * 4608 + sm_off(lr_, lh);
        #pragma unroll
        for (int j = 0; j < 4; ++j) {
            float4 o;
            o.x = tf32r(va[j].x); o.y = tf32r(va[j].y);
            o.z = tf32r(va[j].z); o.w = tf32r(va[j].w);
            ((float4*)dst)[j] = o;
        }
    };
    auto cpB = [&](const Chunk& ch, int bu) {
        uint32_t bd = smB + bu * 18432 + 4 * sm_off(lr_, lh);
        const char* gp = (const char*)(ch.b + (size_t)lr_ * ch.brs + lh * 16);
        #pragma unroll
        for (int j = 0; j < 4; ++j)
            asm volatile("cp.async.ca.shared.global [%0], [%1], 16;"
                         :: "r"(bd + 16u * j), "l"(gp + 16 * j) : "memory");
        asm volatile("cp.async.commit_group;" ::: "memory");
    };

    // prologue
    {
        Chunk c0 = decode(0);
        ldA(c0);
        cpB(c0, 0);
    }

    for (int c = 0; c < TOTAL; ++c) {
        const int bu = c & 1;
        stsA(bu);
        asm volatile("cp.async.wait_group 0;" ::: "memory");
        __syncthreads();
        if (c + 1 < TOTAL) {
            Chunk cn = decode(c + 1);
            ldA(cn);
            cpB(cn, bu ^ 1);
        }
        // ---- compute chunk c ----
        const uint32_t abuf = smA + bu * 18432;
        const uint32_t bbuf = smB + bu * 18432;
        #pragma unroll
        for (int kt = 0; kt < 4; ++kt) {
            const int koA = 4 * ((((kt >> 1) ^ ap) << 4) + (kt & 1) * 8 + acg);
            const int koB = 4 * ((((kt >> 1) ^ bp) << 4) + (kt & 1) * 8 + bcg);
            uint32_t a[4][4];
            #pragma unroll
            for (int mt = 0; mt < 4; ++mt)
                ldsm4(a[mt], abuf + 4 * ((arow + mt * 16) * AW) + koA);
            uint32_t b[4][2];
            #pragma unroll
            for (int p = 0; p < 2; ++p) {
                uint32_t d[4];
                ldsm4(d, bbuf + 4 * ((brow + p * 16) * AW) + koB);
                b[2 * p][0] = d[0]; b[2 * p][1] = d[1];
                b[2 * p + 1][0] = d[2]; b[2 * p + 1][1] = d[3];
            }
            #pragma unroll
            for (int mt = 0; mt < 4; ++mt)
                #pragma unroll
                for (int nt = 0; nt < 4; ++nt)
                    mma_tf32(acc[mt][nt], a[mt], b[nt]);
        }
    }

    // ---- epilogue ----
    #pragma unroll
    for (int mt = 0; mt < 4; ++mt) {
        int row0 = rowBase + warpM * 64 + mt * 16 + (lane >> 2);
        #pragma unroll
        for (int hr = 0; hr < 2; ++hr) {
            int row = row0 + 8 * hr;
            if (row >= M) continue;
            const float* tpr = (MODE == 1) ? (tp + b_idx[row] * 256) : nullptr;
            float* orow = out + (size_t)row * 128;
            #pragma unroll
            for (int nt = 0; nt < 4; ++nt) {
                int col = warpN * 32 + nt * 8 + 2 * (lane & 3);
                float v0 = acc[mt][nt][2 * hr + 0];
                float v1 = acc[mt][nt][2 * hr + 1];
                if (MODE == 1) {
                    v0 = (v0 + bias[col])     * (1.f + tpr[col])     + tpr[128 + col];
                    v1 = (v1 + bias[col + 1]) * (1.f + tpr[col + 1]) + tpr[129 + col];
                } else if (MODE == 2) {
                    v0 += bias[col] + bias2[col];
                    v1 += bias[col + 1] + bias2[col + 1];
                }
                *(float2*)(orow + col) = make_float2(v0, v1);
            }
        }
    }
}

// ---------------- launch ----------------
extern "C" void kernel_launch(void* const* d_in, const int* in_sizes, int n_in,
                              void* d_out, int out_size) {
    const float* x     = (const float*)d_in[0];
    const float* t     = (const float*)d_in[1];
    const int*   b_idx = (const int*)  d_in[2];
    const int*   nbr   = (const int*)  d_in[3];
    const int*   nbrd  = (const int*)  d_in[4];
    const float* g1    = (const float*)d_in[5];
    const float* be1   = (const float*)d_in[6];
    const float* W1    = (const float*)d_in[7];
    const float* b1    = (const float*)d_in[8];
    const float* Wt    = (const float*)d_in[9];
    const float* bt    = (const float*)d_in[10];
    const float* g2    = (const float*)d_in[11];
    const float* be2   = (const float*)d_in[12];
    const float* W2    = (const float*)d_in[13];
    const float* b2    = (const float*)d_in[14];
    const float* Wid   = (const float*)d_in[15];
    const float* bid   = (const float*)d_in[16];
    const float* Wd    = (const float*)d_in[17];
    float* out = (float*)d_out;

    float *pa, *ph, *ph2, *ppart, *pmv, *ptp, *pW1T, *pW2T, *pWiT, *pWdT;
    cudaGetSymbolAddress((void**)&pa,    g_a);
    cudaGetSymbolAddress((void**)&ph,    g_h);
    cudaGetSymbolAddress((void**)&ph2,   g_h2);
    cudaGetSymbolAddress((void**)&ppart, g_part);
    cudaGetSymbolAddress((void**)&pmv,   g_mv);
    cudaGetSymbolAddress((void**)&ptp,   g_tp);
    cudaGetSymbolAddress((void**)&pW1T,  g_W1T);
    cudaGetSymbolAddress((void**)&pW2T,  g_W2T);
    cudaGetSymbolAddress((void**)&pWiT,  g_WiT);
    cudaGetSymbolAddress((void**)&pWdT,  g_WdT);

    cudaFuncSetAttribute(conv_mma_kernel<64, 1>,  cudaFuncAttributeMaxDynamicSharedMemorySize, CONV_SMEM);
    cudaFuncSetAttribute(conv_mma_kernel<128, 2>, cudaFuncAttributeMaxDynamicSharedMemorySize, CONV_SMEM);
    cudaFuncSetAttribute(conv_mma_kernel<128, 0>, cudaFuncAttributeMaxDynamicSharedMemorySize, CONV_SMEM);

    const float invn = 1.0f / (float)NN;
    const int convGrid = (NN + TILE_M - 1) / TILE_M;   // 1563
    const int downGrid = (NDD + TILE_M - 1) / TILE_M;  // 196
    dim3 tb(32, 8);

    // ---- weight prep (transpose + rna tf32) ----
    wprep_kernel<64> <<<dim3(4, 2, 27), tb>>>(W1,  pW1T);
    wprep_kernel<128><<<dim3(4, 4, 27), tb>>>(W2,  pW2T);
    wprep_kernel<64> <<<dim3(4, 2, 1),  tb>>>(Wid, pWiT);
    wprep_kernel<128><<<dim3(4, 4, 8),  tb>>>(Wd,  pWdT);

    // ---- BN1(x) + SiLU -> a ----
    bn_stats_kernel<NI><<<STATS_BLOCKS, 256>>>(x, NN, ppart);
    bn_finalize_kernel<NI><<<1, NI>>>(ppart, STATS_BLOCKS, invn, g1, be1, pmv);
    {
        int n4 = NN * NI / 4;
        bn_apply_silu_kernel<NI><<<(n4 + 255) / 256, 256>>>((const float4*)x, pmv, (float4*)pa, n4);
    }
    // ---- time projection ----
    tproj_kernel<<<1, 256>>>(t, Wt, bt, ptp);
    // ---- conv1 (+bias +FiLM fused) -> h ----
    conv_mma_kernel<64, 1><<<convGrid, 256, CONV_SMEM>>>(
        pa, nbr, pW1T, b1, nullptr, ptp, b_idx, nullptr, nullptr, ph, NN, KK);
    // ---- BN2(h) + SiLU -> a ----
    bn_stats_kernel<NFD><<<STATS_BLOCKS, 256>>>(ph, NN, ppart);
    bn_finalize_kernel<NFD><<<1, NFD>>>(ppart, STATS_BLOCKS, invn, g2, be2, pmv);
    {
        int n4 = NN * NFD / 4;
        bn_apply_silu_kernel<NFD><<<(n4 + 255) / 256, 256>>>((const float4*)ph, pmv, (float4*)pa, n4);
    }
    // ---- conv2 + fused idconv (+b2+bid) -> h2 ----
    conv_mma_kernel<128, 2><<<convGrid, 256, CONV_SMEM>>>(
        pa, nbr, pW2T, b2, bid, nullptr, nullptr, x, pWiT, ph2, NN, KK);
    // ---- strided down conv -> out ----
    conv_mma_kernel<128, 0><<<downGrid, 256, CONV_SMEM>>>(
        ph2, nbrd, pWdT, nullptr, nullptr, nullptr, nullptr, nullptr, nullptr, out, NDD, KDD);

    (void)in_sizes; (void)n_in; (void)out_size;
}